// round 6
// baseline (speedup 1.0000x reference)
#include <cuda_runtime.h>
#include <cuda_bf16.h>
#include <math.h>
#include <stdint.h>

// ---------------- problem constants ----------------
#define BB   2
#define SS   4096
#define HH   1024
#define NKH  8
#define NVH  16
#define DK   64
#define DV   64
#define KEY_DIM   (NKH*DK)            // 512
#define VAL_DIM   (NVH*DV)            // 1024
#define CONV_DIM  (2*KEY_DIM+VAL_DIM) // 2048
#define MM   (BB*SS)                  // 8192 rows
#define NCAT 3200                     // 2048 qkv + 1024 z + 16 a + 16 b + 96 pad
#define GKP  2048                     // physical packed K: [hi(1024) | lo(1024)]
#define KCHUNKS 96                    // logical K' = 3072, BK=32

// ---------------- scratch (static device mem; no allocs allowed) ----------------
__device__ __nv_bfloat16 g_ahl  [(size_t)MM*GKP];    // hidden [hi|lo]
__device__ __nv_bfloat16 g_w16  [(size_t)NCAT*GKP];  // packed weights [hi|lo]
__device__ __nv_bfloat16 g_wo16 [(size_t)HH*GKP];    // W_out [hi|lo]
__device__ __nv_bfloat16 g_hhl  [(size_t)MM*GKP];    // normed h [hi|lo]
__device__ float g_ccat [(size_t)MM*NCAT];           // fused projection output
__device__ float g_conv [(size_t)MM*CONV_DIM];       // after conv+silu
__device__ float g_gate [(size_t)MM*NVH];
__device__ float g_beta [(size_t)MM*NVH];
__device__ float g_o    [(size_t)MM*VAL_DIM];        // scan output

// ================= helpers =================
__device__ __forceinline__ uint32_t smem_u32(const void* p) {
    uint32_t a;
    asm("{ .reg .u64 t; cvta.to.shared.u64 t, %1; cvt.u32.u64 %0, t; }" : "=r"(a) : "l"(p));
    return a;
}
__device__ __forceinline__ void ldsm_x4(uint32_t& r0, uint32_t& r1, uint32_t& r2, uint32_t& r3, uint32_t addr) {
    asm volatile("ldmatrix.sync.aligned.m8n8.x4.shared.b16 {%0,%1,%2,%3}, [%4];"
                 : "=r"(r0), "=r"(r1), "=r"(r2), "=r"(r3) : "r"(addr));
}
__device__ __forceinline__ void mma16816(float* c, uint32_t a0, uint32_t a1, uint32_t a2, uint32_t a3,
                                         uint32_t b0, uint32_t b1) {
    asm volatile("mma.sync.aligned.m16n8k16.row.col.f32.bf16.bf16.f32 "
                 "{%0,%1,%2,%3}, {%4,%5,%6,%7}, {%8,%9}, {%0,%1,%2,%3};"
                 : "+f"(c[0]), "+f"(c[1]), "+f"(c[2]), "+f"(c[3])
                 : "r"(a0), "r"(a1), "r"(a2), "r"(a3), "r"(b0), "r"(b1));
}
#define CP_ASYNC16(dst, src) \
    asm volatile("cp.async.cg.shared.global [%0], [%1], 16;" :: "r"(dst), "l"(src) : "memory")
#define CP_COMMIT() asm volatile("cp.async.commit_group;" ::: "memory")
#define CP_WAIT1()  asm volatile("cp.async.wait_group 1;" ::: "memory")

// ================= split-bf16 conversion kernels (physical [hi|lo]) =================
__global__ void cvt_hidden_kernel(const float* __restrict__ x, __nv_bfloat16* __restrict__ out)
{
    int idx = blockIdx.x * blockDim.x + threadIdx.x;
    if (idx >= MM * HH) return;
    int m = idx >> 10, k = idx & 1023;
    float v = x[idx];
    __nv_bfloat16 hi = __float2bfloat16_rn(v);
    __nv_bfloat16 lo = __float2bfloat16_rn(v - __bfloat162float(hi));
    size_t base = (size_t)m * GKP + k;
    out[base] = hi; out[base + 1024] = lo;
}
__global__ void cvt_w_kernel(const float* __restrict__ Wqkv, const float* __restrict__ Wz,
                             const float* __restrict__ Wa,   const float* __restrict__ Wb,
                             __nv_bfloat16* __restrict__ out)
{
    int idx = blockIdx.x * blockDim.x + threadIdx.x;
    if (idx >= NCAT * HH) return;
    int r = idx >> 10, k = idx & 1023;
    float v = 0.f;
    if      (r < 2048) v = Wqkv[(size_t)r * HH + k];
    else if (r < 3072) v = Wz  [(size_t)(r - 2048) * HH + k];
    else if (r < 3088) v = Wa  [(size_t)(r - 3072) * HH + k];
    else if (r < 3104) v = Wb  [(size_t)(r - 3088) * HH + k];
    __nv_bfloat16 hi = __float2bfloat16_rn(v);
    __nv_bfloat16 lo = __float2bfloat16_rn(v - __bfloat162float(hi));
    size_t base = (size_t)r * GKP + k;
    out[base] = hi; out[base + 1024] = lo;
}
__global__ void cvt_wout_kernel(const float* __restrict__ W, __nv_bfloat16* __restrict__ out)
{
    int idx = blockIdx.x * blockDim.x + threadIdx.x;
    if (idx >= HH * VAL_DIM) return;
    int r = idx >> 10, k = idx & 1023;
    float v = W[idx];
    __nv_bfloat16 hi = __float2bfloat16_rn(v);
    __nv_bfloat16 lo = __float2bfloat16_rn(v - __bfloat162float(hi));
    size_t base = (size_t)r * GKP + k;
    out[base] = hi; out[base + 1024] = lo;
}

// ================= HMMA GEMM with cp.async pipeline =================
// C[M,N] = sum over logical K'=3072: A'[hi|hi|lo] x B'[hi|lo|hi]^T, fp32 acc.
// CTA 128x128, BK=32, 4 warps (2x2), warp tile 64x64, 3-stage cp.async.
#define SPITCH 40                        // smem row pitch in bf16 (80B): conflict-free ldmatrix
#define STAGE_BYTES (128 * SPITCH * 2)   // 10240 B per matrix per stage
#define GEMM_SMEM (6 * STAGE_BYTES)      // 61440 B

__global__ void __launch_bounds__(128, 2) mma_gemm_kernel(
    const __nv_bfloat16* __restrict__ A, const __nv_bfloat16* __restrict__ B,
    float* __restrict__ C, int N)
{
    extern __shared__ char smem[];
    const uint32_t aB = smem_u32(smem);
    const uint32_t bB = aB + 3 * STAGE_BYTES;

    const int tid  = threadIdx.x;
    const int lane = tid & 31;
    const int wid  = tid >> 5;
    const int warpM = wid & 1;
    const int warpN = wid >> 1;
    const int bm = blockIdx.y * 128;
    const int bn = blockIdx.x * 128;

    // global row pointers: thread t owns row t for cp.async (4x16B = 32 elems per stage)
    const __nv_bfloat16* Agr = A + (size_t)(bm + tid) * GKP;
    const __nv_bfloat16* Bgr = B + (size_t)(bn + tid) * GKP;
    const uint32_t stA = aB + tid * (SPITCH * 2);
    const uint32_t stB = bB + tid * (SPITCH * 2);

    auto issue = [&](int c) {
        int s = c % 3;
        int ao = (c < 64) ? (c & 31) * 32 : 1024 + (c - 64) * 32;            // A: [hi|hi|lo]
        int bo = (c < 32) ? c * 32 : ((c < 64) ? 1024 + (c - 32) * 32 : (c - 64) * 32); // B: [hi|lo|hi]
        const char* ga = (const char*)(Agr + ao);
        const char* gb = (const char*)(Bgr + bo);
        uint32_t sa = stA + s * STAGE_BYTES;
        uint32_t sb = stB + s * STAGE_BYTES;
#pragma unroll
        for (int j = 0; j < 4; j++) {
            CP_ASYNC16(sa + j * 16, ga + j * 16);
            CP_ASYNC16(sb + j * 16, gb + j * 16);
        }
        CP_COMMIT();
    };

    // ldmatrix address components
    const uint32_t aRow = warpM * 64 + (lane & 15);
    const uint32_t aSel = (lane >> 4) * 16;                 // k-half byte sel
    const uint32_t bRow = warpN * 64 + (lane & 7) + ((lane >> 4) & 1) * 8;
    const uint32_t bSel = ((lane >> 3) & 1) * 16;

    float acc[4][8][4];
#pragma unroll
    for (int i = 0; i < 4; i++)
#pragma unroll
        for (int j = 0; j < 8; j++)
#pragma unroll
            for (int x = 0; x < 4; x++) acc[i][j][x] = 0.f;

    issue(0); issue(1);

    for (int c = 0; c < KCHUNKS; c++) {
        CP_WAIT1();
        __syncthreads();
        if (c + 2 < KCHUNKS) issue(c + 2);

        const int s = c % 3;
        const uint32_t aBase = aB + s * STAGE_BYTES;
        const uint32_t bBase = bB + s * STAGE_BYTES;
#pragma unroll
        for (int kk = 0; kk < 2; kk++) {
            uint32_t af[4][4], bfr[8][2];
#pragma unroll
            for (int mi = 0; mi < 4; mi++)
                ldsm_x4(af[mi][0], af[mi][1], af[mi][2], af[mi][3],
                        aBase + (aRow + mi * 16) * (SPITCH * 2) + kk * 32 + aSel);
#pragma unroll
            for (int nb = 0; nb < 4; nb++) {
                uint32_t r0, r1, r2, r3;
                ldsm_x4(r0, r1, r2, r3,
                        bBase + (bRow + nb * 16) * (SPITCH * 2) + kk * 32 + bSel);
                bfr[2*nb][0] = r0; bfr[2*nb][1] = r1;
                bfr[2*nb+1][0] = r2; bfr[2*nb+1][1] = r3;
            }
#pragma unroll
            for (int mi = 0; mi < 4; mi++)
#pragma unroll
                for (int nj = 0; nj < 8; nj++)
                    mma16816(acc[mi][nj], af[mi][0], af[mi][1], af[mi][2], af[mi][3],
                             bfr[nj][0], bfr[nj][1]);
        }
    }

    // epilogue
    const int erow = bm + warpM * 64 + (lane >> 2);
    const int ecol = bn + warpN * 64 + (lane & 3) * 2;
#pragma unroll
    for (int mi = 0; mi < 4; mi++) {
#pragma unroll
        for (int nj = 0; nj < 8; nj++) {
            float* C0 = C + (size_t)(erow + mi * 16) * N + ecol + nj * 8;
            float* C1 = C + (size_t)(erow + mi * 16 + 8) * N + ecol + nj * 8;
            *(float2*)C0 = make_float2(acc[mi][nj][0], acc[mi][nj][1]);
            *(float2*)C1 = make_float2(acc[mi][nj][2], acc[mi][nj][3]);
        }
    }
}

// ---------------- depthwise causal conv (k=4) + silu ----------------
__global__ void conv_silu_kernel(const float* __restrict__ ccat,
                                 const float* __restrict__ conv_w,
                                 float* __restrict__ out)
{
    size_t idx = (size_t)blockIdx.x * blockDim.x + threadIdx.x;
    if (idx >= (size_t)MM * CONV_DIM) return;
    int c  = (int)(idx & (CONV_DIM - 1));
    int bs = (int)(idx >> 11);
    int s  = bs & (SS - 1);
    float w0 = conv_w[c*4+0], w1 = conv_w[c*4+1], w2 = conv_w[c*4+2], w3 = conv_w[c*4+3];
    const float* p = ccat + (size_t)bs * NCAT + c;
    float acc = p[0] * w3;
    if (s >= 1) acc = fmaf(p[-NCAT],   w2, acc);
    if (s >= 2) acc = fmaf(p[-2*NCAT], w1, acc);
    if (s >= 3) acc = fmaf(p[-3*NCAT], w0, acc);
    out[idx] = acc / (1.f + expf(-acc));
}

// ---------------- gate epilogue ----------------
__global__ void gate_kernel(const float* __restrict__ ccat,
                            const float* __restrict__ dt_bias,
                            const float* __restrict__ A_log,
                            float* __restrict__ gg, float* __restrict__ gb)
{
    int idx = blockIdx.x * blockDim.x + threadIdx.x;
    if (idx >= MM * NVH) return;
    int h = idx & 15;
    int m = idx >> 4;
    float a = ccat[(size_t)m * NCAT + 3072 + h];
    float b = ccat[(size_t)m * NCAT + 3088 + h];
    float x  = a + dt_bias[h];
    float sp = (x > 20.f) ? x : log1pf(expf(x));
    gg[idx]  = -expf(A_log[h]) * sp;
    gb[idx]  = 1.f / (1.f + expf(-b));
}

// ---------------- gated delta-rule scan ----------------
struct ScanStep { float4 ka, kb, qa, qb; float v, g, b; };

__global__ void __launch_bounds__(128, 1) scan_kernel(
    const float* __restrict__ qkv, const float* __restrict__ gg,
    const float* __restrict__ gb,  float* __restrict__ o_out)
{
    const int blk = blockIdx.x;
    const int bh  = blk >> 2;
    const int b   = bh >> 4;
    const int h   = bh & 15;
    const int grp = blk & 3;
    const int tid = threadIdx.x;
    const int col = grp * 16 + (tid >> 3);
    const int rp  = tid & 7;
    const int r0  = rp * 8;
    const int kq  = h >> 1;

    const float* qbase = qkv + (size_t)b * SS * CONV_DIM + (size_t)kq * DK + r0;
    const float* kbase = qbase + KEY_DIM;
    const float* vbase = qkv + (size_t)b * SS * CONV_DIM + 2*KEY_DIM + h * DV + col;
    const float* gbase = gg + (size_t)b * SS * NVH + h;
    const float* bbase = gb + (size_t)b * SS * NVH + h;
    float*       obase = o_out + (size_t)b * SS * VAL_DIM + h * DV + col;

    float S[8];
#pragma unroll
    for (int i = 0; i < 8; i++) S[i] = 0.f;

    auto load = [&](ScanStep& p, int t) {
        size_t off = (size_t)t * CONV_DIM;
        p.ka = *(const float4*)(kbase + off);
        p.kb = *(const float4*)(kbase + off + 4);
        p.qa = *(const float4*)(qbase + off);
        p.qb = *(const float4*)(qbase + off + 4);
        p.v  = vbase[off];
        p.g  = gbase[(size_t)t * NVH];
        p.b  = bbase[(size_t)t * NVH];
    };

    auto compute = [&](const ScanStep& p, int t) {
        float eg = expf(p.g);
        float kr[8] = {p.ka.x,p.ka.y,p.ka.z,p.ka.w,p.kb.x,p.kb.y,p.kb.z,p.kb.w};
        float qr[8] = {p.qa.x,p.qa.y,p.qa.z,p.qa.w,p.qb.x,p.qb.y,p.qb.z,p.qb.w};
        float d0 = 0.f, d1 = 0.f;
#pragma unroll
        for (int i = 0; i < 8; i += 2) {
            d0 = fmaf(S[i],   kr[i],   d0);
            d1 = fmaf(S[i+1], kr[i+1], d1);
        }
        float d = d0 + d1;
        d += __shfl_xor_sync(0xffffffffu, d, 1);
        d += __shfl_xor_sync(0xffffffffu, d, 2);
        d += __shfl_xor_sync(0xffffffffu, d, 4);
        float delta = p.b * (p.v - eg * d);
        float o0 = 0.f, o1 = 0.f;
#pragma unroll
        for (int i = 0; i < 8; i++) {
            S[i] = fmaf(S[i], eg, kr[i] * delta);
            if (i & 1) o1 = fmaf(S[i], qr[i], o1);
            else       o0 = fmaf(S[i], qr[i], o0);
        }
        float op = o0 + o1;
        op += __shfl_xor_sync(0xffffffffu, op, 1);
        op += __shfl_xor_sync(0xffffffffu, op, 2);
        op += __shfl_xor_sync(0xffffffffu, op, 4);
        if (rp == 0) obase[(size_t)t * VAL_DIM] = op * 0.125f;
    };

    ScanStep p0, p1, p2, p3;
    load(p0, 0); load(p1, 1); load(p2, 2); load(p3, 3);
    for (int t = 0; t < SS; t += 4) {
        compute(p0, t);   if (t + 4 < SS) load(p0, t + 4);
        compute(p1, t+1); if (t + 5 < SS) load(p1, t + 5);
        compute(p2, t+2); if (t + 6 < SS) load(p2, t + 6);
        compute(p3, t+3); if (t + 7 < SS) load(p3, t + 7);
    }
}

// ---------------- gated RMSNorm -> split-bf16 [hi|lo] output ----------------
__global__ void gated_norm_kernel(const float* __restrict__ o,
                                  const float* __restrict__ ccat,
                                  const float* __restrict__ nw,
                                  __nv_bfloat16* __restrict__ hhl)
{
    int warp = threadIdx.x >> 5, lane = threadIdx.x & 31;
    size_t idx = (size_t)blockIdx.x * 8 + warp;
    int m  = (int)(idx >> 4);
    int hd = (int)(idx & 15);
    size_t base  = idx * DV;
    size_t zbase = (size_t)m * NCAT + 2048 + hd * DV;
    float o0 = o[base + lane],       o1 = o[base + lane + 32];
    float z0 = ccat[zbase + lane],   z1 = ccat[zbase + lane + 32];
    float h0 = o0 * (z0 / (1.f + expf(-z0)));
    float h1 = o1 * (z1 / (1.f + expf(-z1)));
    float ss = h0*h0 + h1*h1;
#pragma unroll
    for (int off = 16; off > 0; off >>= 1)
        ss += __shfl_xor_sync(0xffffffffu, ss, off);
    float scale = rsqrtf(ss * (1.f / DV) + 1e-6f);
    h0 *= scale * nw[lane];
    h1 *= scale * nw[lane + 32];

    int c0 = hd * 64 + lane;
    size_t b3 = (size_t)m * GKP + c0;
    __nv_bfloat16 hi0 = __float2bfloat16_rn(h0);
    __nv_bfloat16 lo0 = __float2bfloat16_rn(h0 - __bfloat162float(hi0));
    __nv_bfloat16 hi1 = __float2bfloat16_rn(h1);
    __nv_bfloat16 lo1 = __float2bfloat16_rn(h1 - __bfloat162float(hi1));
    hhl[b3]             = hi0; hhl[b3 + 1024]      = lo0;
    hhl[b3 + 32]        = hi1; hhl[b3 + 32 + 1024] = lo1;
}

// ---------------- driver ----------------
extern "C" void kernel_launch(void* const* d_in, const int* in_sizes, int n_in,
                              void* d_out, int out_size)
{
    const float* hidden  = (const float*)d_in[0];
    const float* W_qkv   = (const float*)d_in[1];
    const float* conv_w  = (const float*)d_in[2];
    const float* W_z     = (const float*)d_in[3];
    const float* W_b     = (const float*)d_in[4];
    const float* W_a     = (const float*)d_in[5];
    const float* dt_bias = (const float*)d_in[6];
    const float* A_log   = (const float*)d_in[7];
    const float* norm_w  = (const float*)d_in[8];
    const float* W_out   = (const float*)d_in[9];
    float* out = (float*)d_out;

    __nv_bfloat16 *ahl, *w16, *wo16, *hhl;
    float *ccat, *conv, *gg, *gb, *ov;
    cudaGetSymbolAddress((void**)&ahl,  g_ahl);
    cudaGetSymbolAddress((void**)&w16,  g_w16);
    cudaGetSymbolAddress((void**)&wo16, g_wo16);
    cudaGetSymbolAddress((void**)&hhl,  g_hhl);
    cudaGetSymbolAddress((void**)&ccat, g_ccat);
    cudaGetSymbolAddress((void**)&conv, g_conv);
    cudaGetSymbolAddress((void**)&gg,   g_gate);
    cudaGetSymbolAddress((void**)&gb,   g_beta);
    cudaGetSymbolAddress((void**)&ov,   g_o);

    cudaFuncSetAttribute(mma_gemm_kernel, cudaFuncAttributeMaxDynamicSharedMemorySize, GEMM_SMEM);

    // 0) split-bf16 conversions ([hi|lo] packed)
    cvt_hidden_kernel<<<(MM*HH + 255) / 256, 256>>>(hidden, ahl);
    cvt_w_kernel<<<(NCAT*HH + 255) / 256, 256>>>(W_qkv, W_z, W_a, W_b, w16);
    cvt_wout_kernel<<<(HH*VAL_DIM + 255) / 256, 256>>>(W_out, wo16);
    // 1) Ccat = hidden @ Wcat^T  [8192, 3200]
    mma_gemm_kernel<<<dim3(NCAT/128, MM/128), 128, GEMM_SMEM>>>(ahl, w16, ccat, NCAT);
    // 2) depthwise causal conv + silu
    {
        size_t n = (size_t)MM * CONV_DIM;
        conv_silu_kernel<<<(unsigned)((n + 255) / 256), 256>>>(ccat, conv_w, conv);
    }
    // 3) gate / beta
    gate_kernel<<<(MM*NVH + 255) / 256, 256>>>(ccat, dt_bias, A_log, gg, gb);
    // 4) gated delta-rule scan
    scan_kernel<<<BB*NVH*4, 128>>>(conv, gg, gb, ov);
    // 5) gated RMSNorm -> split bf16
    gated_norm_kernel<<<(MM*NVH)/8, 256>>>(ov, ccat, norm_w, hhl);
    // 6) out = h @ W_out^T  [8192, 1024]
    mma_gemm_kernel<<<dim3(HH/128, MM/128), 128, GEMM_SMEM>>>(hhl, wo16, out, HH);
}